// round 1
// baseline (speedup 1.0000x reference)
#include <cuda_runtime.h>
#include <math.h>

#define QLEN 512
#define BATCH 4
#define DMODEL 1024
#define NLAYER 4
#define NHEAD 16
#define DHEAD 64
#define DINNER 4096
#define MLEN 512
#define KLEN 1024
#define BH (BATCH*NHEAD)

// ---------------- scratch (device globals; allocation-free) ----------------
__device__ float g_cat[(size_t)KLEN*BATCH*DMODEL];          // 16.8 MB
__device__ float g_heads[(size_t)KLEN*BATCH*3*DMODEL];      // 50 MB
__device__ float g_r[(size_t)KLEN*DMODEL];                  // 4 MB
__device__ float g_rk[(size_t)KLEN*DMODEL];                 // 4 MB
__device__ float g_ac[(size_t)BH*QLEN*KLEN];                // 134 MB
__device__ float g_bd[(size_t)BH*QLEN*KLEN];                // 134 MB
__device__ float g_av[(size_t)QLEN*BATCH*DMODEL];           // 8.4 MB
__device__ float g_tmp[(size_t)QLEN*BATCH*DMODEL];          // 8.4 MB
__device__ float g_h[(size_t)QLEN*BATCH*DMODEL];            // 8.4 MB
__device__ float g_ff[(size_t)QLEN*BATCH*DINNER];           // 33.5 MB

// ---------------- position embedding ----------------
__global__ void posemb_kernel(float* __restrict__ r) {
    int idx = blockIdx.x * 256 + threadIdx.x;   // 1024*1024
    int k = idx >> 10, d = idx & 1023;
    float pos = (float)(KLEN - 1 - k);
    int j = (d < 512) ? d : d - 512;
    float inv = expf(-((float)(2 * j) / 1024.0f) * 9.210340371976184f); // ln(10000)
    float ang = pos * inv;
    r[idx] = (d < 512) ? sinf(ang) : cosf(ang);
}

// ---------------- simple vector copy (float4) ----------------
__global__ void copy4_kernel(float4* __restrict__ dst, const float4* __restrict__ src) {
    size_t i = (size_t)blockIdx.x * 256 + threadIdx.x;
    dst[i] = src[i];
}

// ---------------- concat mems[l] (512 rows) + h (512 rows) -> cat ----------------
__global__ void concat_kernel(float4* __restrict__ cat, const float4* __restrict__ mem,
                              const float4* __restrict__ h) {
    size_t i = (size_t)blockIdx.x * 256 + threadIdx.x;    // over float4, total (1024*4*1024)/4
    const size_t half = (size_t)MLEN * BATCH * DMODEL / 4;
    cat[i] = (i < half) ? mem[i] : h[i - half];
}

// ---------------- classic SGEMM 128x128x8, 256 threads, 8x8 per thread ----------------
template<int RELU, int HASBIAS>
__global__ void __launch_bounds__(256) sgemm_kernel(
    const float* __restrict__ A, const float* __restrict__ B,
    const float* __restrict__ bias, float* __restrict__ C,
    int M, int N, int K)
{
    __shared__ float As[8][128];
    __shared__ float Bs[8][128];
    int tid = threadIdx.x;
    int bx = blockIdx.x, by = blockIdx.y;
    const float* Ab = A + (size_t)by * 128 * K;
    const float* Bb = B + (size_t)bx * 128;

    int aRow = tid >> 1;
    int aCol = (tid & 1) * 4;
    int bRow = tid >> 5;
    int bCol = (tid & 31) * 4;
    int ty = tid >> 4, tx = tid & 15;

    float acc[8][8];
#pragma unroll
    for (int i = 0; i < 8; i++)
#pragma unroll
        for (int j = 0; j < 8; j++) acc[i][j] = 0.f;

    for (int k0 = 0; k0 < K; k0 += 8) {
        float4 a4 = *(const float4*)(Ab + (size_t)aRow * K + k0 + aCol);
        float4 b4 = *(const float4*)(Bb + (size_t)(k0 + bRow) * N + bCol);
        As[aCol + 0][aRow] = a4.x;
        As[aCol + 1][aRow] = a4.y;
        As[aCol + 2][aRow] = a4.z;
        As[aCol + 3][aRow] = a4.w;
        *(float4*)&Bs[bRow][bCol] = b4;
        __syncthreads();
#pragma unroll
        for (int k = 0; k < 8; k++) {
            float ar[8], br[8];
            *(float4*)(ar)     = *(const float4*)&As[k][ty * 8];
            *(float4*)(ar + 4) = *(const float4*)&As[k][ty * 8 + 4];
            *(float4*)(br)     = *(const float4*)&Bs[k][tx * 8];
            *(float4*)(br + 4) = *(const float4*)&Bs[k][tx * 8 + 4];
#pragma unroll
            for (int i = 0; i < 8; i++)
#pragma unroll
                for (int j = 0; j < 8; j++) acc[i][j] += ar[i] * br[j];
        }
        __syncthreads();
    }

#pragma unroll
    for (int i = 0; i < 8; i++) {
        size_t row = (size_t)by * 128 + ty * 8 + i;
        float* crow = C + row * N + bx * 128 + tx * 8;
        float out[8];
#pragma unroll
        for (int j = 0; j < 8; j++) {
            float v = acc[i][j];
            if (HASBIAS) v += bias[bx * 128 + tx * 8 + j];
            if (RELU) v = fmaxf(v, 0.f);
            out[j] = v;
        }
        *(float4*)(crow)     = *(float4*)(out);
        *(float4*)(crow + 4) = *(float4*)(out + 4);
    }
}

// ---------------- batched score GEMM: out[bh,i,j] = sum_d (q[i,d]+uv[d]) * k[j,d] ----
// mode 0: k = kh rows from heads (AC);  mode 1: k = rk rows (BD raw, over jj coordinate)
__global__ void __launch_bounds__(256) score_kernel(
    const float* __restrict__ heads, const float* __restrict__ rk,
    const float* __restrict__ uv, float* __restrict__ out, int mode)
{
    int i0 = blockIdx.x * 64;
    int j0 = blockIdx.y * 64;
    int bh = blockIdx.z;
    int b = bh / NHEAD, n = bh % NHEAD;

    __shared__ float sQ[64][68];   // [d][i]
    __shared__ float sK[64][68];   // [d][j]

    int tid = threadIdx.x;
    {
        int i = tid >> 2;
        int dbase = (tid & 3) * 16;
        const float* qrow = heads + ((size_t)(MLEN + i0 + i) * BATCH + b) * 3072 + n * 64;
        const float* uvp = uv + n * 64;
        const float* krow;
        if (mode == 0) krow = heads + ((size_t)(j0 + i) * BATCH + b) * 3072 + 1024 + n * 64;
        else           krow = rk + (size_t)(j0 + i) * 1024 + n * 64;
#pragma unroll
        for (int c = 0; c < 4; c++) {
            float4 q4 = *(const float4*)(qrow + dbase + c * 4);
            float4 u4 = *(const float4*)(uvp + dbase + c * 4);
            float4 k4 = *(const float4*)(krow + dbase + c * 4);
            sQ[dbase + c * 4 + 0][i] = q4.x + u4.x;
            sQ[dbase + c * 4 + 1][i] = q4.y + u4.y;
            sQ[dbase + c * 4 + 2][i] = q4.z + u4.z;
            sQ[dbase + c * 4 + 3][i] = q4.w + u4.w;
            sK[dbase + c * 4 + 0][i] = k4.x;
            sK[dbase + c * 4 + 1][i] = k4.y;
            sK[dbase + c * 4 + 2][i] = k4.z;
            sK[dbase + c * 4 + 3][i] = k4.w;
        }
    }
    __syncthreads();

    int ty = tid >> 4, tx = tid & 15;
    float acc[4][4];
#pragma unroll
    for (int i = 0; i < 4; i++)
#pragma unroll
        for (int j = 0; j < 4; j++) acc[i][j] = 0.f;

#pragma unroll 8
    for (int d = 0; d < 64; d++) {
        float4 a = *(const float4*)&sQ[d][ty * 4];
        float4 bb = *(const float4*)&sK[d][tx * 4];
        float ar[4] = {a.x, a.y, a.z, a.w};
        float br[4] = {bb.x, bb.y, bb.z, bb.w};
#pragma unroll
        for (int i = 0; i < 4; i++)
#pragma unroll
            for (int j = 0; j < 4; j++) acc[i][j] += ar[i] * br[j];
    }

    float* obase = out + ((size_t)bh * QLEN + i0) * KLEN + j0;
#pragma unroll
    for (int i = 0; i < 4; i++) {
        float4 v = {acc[i][0], acc[i][1], acc[i][2], acc[i][3]};
        *(float4*)(obase + (size_t)(ty * 4 + i) * KLEN + tx * 4) = v;
    }
}

// ---------------- fused shift + mask + scale + softmax ----------------
// score[i,j] = 0.125*(AC[i,j] + BDraw[i, j+QLEN-1-i]) for j <= i+MLEN, else -inf
__global__ void __launch_bounds__(256) softmax_kernel(float* ac, const float* __restrict__ bd) {
    int i = blockIdx.x;
    int bh = blockIdx.y;
    float* acrow = ac + ((size_t)bh * QLEN + i) * KLEN;
    const float* bdrow = bd + ((size_t)bh * QLEN + i) * KLEN;
    int tid = threadIdx.x;
    __shared__ float red[256];
    int jmax = i + MLEN;         // inclusive
    int shift = QLEN - 1 - i;
    float v[4];
    float m = -1e30f;
#pragma unroll
    for (int c = 0; c < 4; c++) {
        int j = c * 256 + tid;
        float s = (j <= jmax) ? 0.125f * (acrow[j] + bdrow[j + shift]) : -1e30f;
        v[c] = s;
        m = fmaxf(m, s);
    }
    red[tid] = m; __syncthreads();
    for (int o = 128; o > 0; o >>= 1) {
        if (tid < o) red[tid] = fmaxf(red[tid], red[tid + o]);
        __syncthreads();
    }
    m = red[0]; __syncthreads();
    float sum = 0.f;
#pragma unroll
    for (int c = 0; c < 4; c++) { v[c] = expf(v[c] - m); sum += v[c]; }
    red[tid] = sum; __syncthreads();
    for (int o = 128; o > 0; o >>= 1) {
        if (tid < o) red[tid] += red[tid + o];
        __syncthreads();
    }
    float inv = 1.0f / red[0];
#pragma unroll
    for (int c = 0; c < 4; c++) acrow[c * 256 + tid] = v[c] * inv;
}

// ---------------- AV: av[i,b,n*64+d] = sum_j P[bh,i,j] * vh[j,b,n,d] ----------------
__global__ void __launch_bounds__(256) av_kernel(
    const float* __restrict__ attn, const float* __restrict__ heads, float* __restrict__ av)
{
    int i0 = blockIdx.x * 64;
    int bh = blockIdx.y;
    int b = bh / NHEAD, n = bh % NHEAD;

    __shared__ float sP[64][68];   // [j_local][i]
    __shared__ float sV[64][64];   // [j_local][d]

    int tid = threadIdx.x;
    int ty = tid >> 4, tx = tid & 15;
    float acc[4][4];
#pragma unroll
    for (int i = 0; i < 4; i++)
#pragma unroll
        for (int j = 0; j < 4; j++) acc[i][j] = 0.f;

    for (int j0 = 0; j0 < KLEN; j0 += 64) {
        {
            int i = tid >> 2;
            int jb = (tid & 3) * 16;
            const float* prow = attn + ((size_t)bh * QLEN + i0 + i) * KLEN + j0 + jb;
#pragma unroll
            for (int c = 0; c < 16; c++) sP[jb + c][i] = prow[c];

            int j = tid >> 2;
            int db = (tid & 3) * 16;
            const float* vrow = heads + ((size_t)(j0 + j) * BATCH + b) * 3072 + 2048 + n * 64 + db;
#pragma unroll
            for (int c = 0; c < 4; c++)
                *(float4*)&sV[j][db + c * 4] = *(const float4*)(vrow + c * 4);
        }
        __syncthreads();
#pragma unroll 8
        for (int j = 0; j < 64; j++) {
            float4 p = *(const float4*)&sP[j][ty * 4];
            float4 vv = *(const float4*)&sV[j][tx * 4];
            float pr[4] = {p.x, p.y, p.z, p.w};
            float vr[4] = {vv.x, vv.y, vv.z, vv.w};
#pragma unroll
            for (int i = 0; i < 4; i++)
#pragma unroll
                for (int d = 0; d < 4; d++) acc[i][d] += pr[i] * vr[d];
        }
        __syncthreads();
    }

#pragma unroll
    for (int i = 0; i < 4; i++) {
        float4 v = {acc[i][0], acc[i][1], acc[i][2], acc[i][3]};
        *(float4*)(av + ((size_t)(i0 + ty * 4 + i) * BATCH + b) * DMODEL + n * 64 + tx * 4) = v;
    }
}

// ---------------- residual add + LayerNorm, writes back into h ----------------
__global__ void __launch_bounds__(256) add_ln_kernel(
    float* __restrict__ h, const float* __restrict__ t,
    const float* __restrict__ g, const float* __restrict__ b)
{
    int row = blockIdx.x;
    int tid = threadIdx.x;
    __shared__ float rs[256], rs2[256];
    float x[4];
    float s = 0.f, ss = 0.f;
#pragma unroll
    for (int c = 0; c < 4; c++) {
        int d = c * 256 + tid;
        float v = h[(size_t)row * 1024 + d] + t[(size_t)row * 1024 + d];
        x[c] = v; s += v; ss += v * v;
    }
    rs[tid] = s; rs2[tid] = ss; __syncthreads();
    for (int o = 128; o > 0; o >>= 1) {
        if (tid < o) { rs[tid] += rs[tid + o]; rs2[tid] += rs2[tid + o]; }
        __syncthreads();
    }
    float mu = rs[0] * (1.0f / 1024.0f);
    float var = rs2[0] * (1.0f / 1024.0f) - mu * mu;
    float inv = rsqrtf(var + 1e-5f);
#pragma unroll
    for (int c = 0; c < 4; c++) {
        int d = c * 256 + tid;
        h[(size_t)row * 1024 + d] = (x[c] - mu) * inv * g[d] + b[d];
    }
}

// ---------------- launch ----------------
extern "C" void kernel_launch(void* const* d_in, const int* in_sizes, int n_in,
                              void* d_out, int out_size) {
    (void)in_sizes; (void)n_in; (void)out_size;
    const float* x     = (const float*)d_in[0];
    const float* mems  = (const float*)d_in[1];
    const float* u     = (const float*)d_in[2];
    const float* v     = (const float*)d_in[3];
    const float* W_qkv = (const float*)d_in[4];
    const float* W_o   = (const float*)d_in[5];
    const float* W_r   = (const float*)d_in[6];
    const float* ln1_g = (const float*)d_in[7];
    const float* ln1_b = (const float*)d_in[8];
    const float* W1    = (const float*)d_in[9];
    const float* b1    = (const float*)d_in[10];
    const float* W2    = (const float*)d_in[11];
    const float* b2    = (const float*)d_in[12];
    const float* ln2_g = (const float*)d_in[13];
    const float* ln2_b = (const float*)d_in[14];

    float *cat, *heads, *r, *rk, *ac, *bd, *av, *tmp, *h, *ff;
    cudaGetSymbolAddress((void**)&cat,   g_cat);
    cudaGetSymbolAddress((void**)&heads, g_heads);
    cudaGetSymbolAddress((void**)&r,     g_r);
    cudaGetSymbolAddress((void**)&rk,    g_rk);
    cudaGetSymbolAddress((void**)&ac,    g_ac);
    cudaGetSymbolAddress((void**)&bd,    g_bd);
    cudaGetSymbolAddress((void**)&av,    g_av);
    cudaGetSymbolAddress((void**)&tmp,   g_tmp);
    cudaGetSymbolAddress((void**)&h,     g_h);
    cudaGetSymbolAddress((void**)&ff,    g_ff);

    posemb_kernel<<<4096, 256>>>(r);
    copy4_kernel<<<2048, 256>>>((float4*)h, (const float4*)x);   // 512*4*1024/4

    for (int l = 0; l < NLAYER; l++) {
        concat_kernel<<<4096, 256>>>((float4*)cat,
                                     (const float4*)(mems + (size_t)l * MLEN * BATCH * DMODEL),
                                     (const float4*)h);
        // heads = cat[4096,1024] @ W_qkv[l] [1024,3072]
        sgemm_kernel<0,0><<<dim3(3072/128, 4096/128), 256>>>(
            cat, W_qkv + (size_t)l * DMODEL * 3072, nullptr, heads, 4096, 3072, 1024);
        // rk = r[1024,1024] @ W_r[l]
        sgemm_kernel<0,0><<<dim3(8, 8), 256>>>(
            r, W_r + (size_t)l * DMODEL * DMODEL, nullptr, rk, 1024, 1024, 1024);
        // AC and BDraw
        score_kernel<<<dim3(QLEN/64, KLEN/64, BH), 256>>>(heads, rk, u, ac, 0);
        score_kernel<<<dim3(QLEN/64, KLEN/64, BH), 256>>>(heads, rk, v, bd, 1);
        // shift + mask + softmax (in-place into ac)
        softmax_kernel<<<dim3(QLEN, BH), 256>>>(ac, bd);
        // AV
        av_kernel<<<dim3(QLEN/64, BH), 256>>>(ac, heads, av);
        // O projection
        sgemm_kernel<0,0><<<dim3(8, 16), 256>>>(
            av, W_o + (size_t)l * DMODEL * DMODEL, nullptr, tmp, 2048, 1024, 1024);
        add_ln_kernel<<<2048, 256>>>(h, tmp, ln1_g + (size_t)l * DMODEL, ln1_b + (size_t)l * DMODEL);
        // FFN
        sgemm_kernel<1,1><<<dim3(4096/128, 16), 256>>>(
            h, W1 + (size_t)l * DMODEL * DINNER, b1 + (size_t)l * DINNER, ff, 2048, 4096, 1024);
        sgemm_kernel<0,1><<<dim3(8, 16), 256>>>(
            ff, W2 + (size_t)l * DINNER * DMODEL, b2 + (size_t)l * DMODEL, tmp, 2048, 1024, 4096);
        add_ln_kernel<<<2048, 256>>>(h, tmp, ln2_g + (size_t)l * DMODEL, ln2_b + (size_t)l * DMODEL);
    }

    cudaMemcpyAsync(d_out, h, (size_t)QLEN * BATCH * DMODEL * sizeof(float),
                    cudaMemcpyDeviceToDevice);
}

// round 2
// speedup vs baseline: 1.7708x; 1.7708x over previous
#include <cuda_runtime.h>
#include <math.h>
#include <stdint.h>

#define QLEN 512
#define BATCH 4
#define DMODEL 1024
#define NLAYER 4
#define NHEAD 16
#define DHEAD 64
#define DINNER 4096
#define MLEN 512
#define KLEN 1024
#define BH (BATCH*NHEAD)

// ---------------- scratch (device globals; allocation-free) ----------------
__device__ float g_cat[(size_t)KLEN*BATCH*DMODEL];
__device__ float g_heads[(size_t)KLEN*BATCH*3*DMODEL];
__device__ float g_r[(size_t)KLEN*DMODEL];
__device__ float g_rk[(size_t)KLEN*DMODEL];
__device__ float g_ac[(size_t)BH*QLEN*KLEN];
__device__ float g_bd[(size_t)BH*QLEN*KLEN];
__device__ float g_av[(size_t)QLEN*BATCH*DMODEL];
__device__ float g_tmp[(size_t)QLEN*BATCH*DMODEL];
__device__ float g_h[(size_t)QLEN*BATCH*DMODEL];
__device__ float g_ff[(size_t)QLEN*BATCH*DINNER];

__device__ __forceinline__ uint32_t f2tf32(float f) {
    uint32_t o;
    asm("cvt.rna.tf32.f32 %0, %1;" : "=r"(o) : "f"(f));
    return o;
}

// ---------------- position embedding ----------------
__global__ void posemb_kernel(float* __restrict__ r) {
    int idx = blockIdx.x * 256 + threadIdx.x;
    int k = idx >> 10, d = idx & 1023;
    float pos = (float)(KLEN - 1 - k);
    int j = (d < 512) ? d : d - 512;
    float inv = expf(-((float)(2 * j) / 1024.0f) * 9.210340371976184f);
    float ang = pos * inv;
    r[idx] = (d < 512) ? sinf(ang) : cosf(ang);
}

__global__ void copy4_kernel(float4* __restrict__ dst, const float4* __restrict__ src) {
    size_t i = (size_t)blockIdx.x * 256 + threadIdx.x;
    dst[i] = src[i];
}

__global__ void concat_kernel(float4* __restrict__ cat, const float4* __restrict__ mem,
                              const float4* __restrict__ h) {
    size_t i = (size_t)blockIdx.x * 256 + threadIdx.x;
    const size_t half = (size_t)MLEN * BATCH * DMODEL / 4;
    cat[i] = (i < half) ? mem[i] : h[i - half];
}

// ---------------- TF32 tensor-core GEMM: C[M,N] = A[M,K] @ B[K,N] ----------------
// 128x128 CTA tile, BK=32, 256 threads = 8 warps (2 M x 4 N), warp tile 64x32.
// mma.sync.aligned.m16n8k8 tf32. A,B converted to tf32 on smem store.
template<int RELU, int HASBIAS>
__global__ void __launch_bounds__(256, 2) tf32gemm_kernel(
    const float* __restrict__ A, const float* __restrict__ B,
    const float* __restrict__ bias, float* __restrict__ C,
    int M, int N, int K)
{
    __shared__ uint32_t As[128][36];   // [m][k], pad 4
    __shared__ uint32_t Bs[32][132];   // [k][n], pad 4

    int tid  = threadIdx.x;
    int lane = tid & 31;
    int warp = tid >> 5;
    int wm = warp >> 2;       // 0..1
    int wn = warp & 3;        // 0..3
    int bx = blockIdx.x, by = blockIdx.y;

    // gmem load coords
    int aRow = tid >> 1;             // 0..127
    int aCol = (tid & 1) * 16;       // 0 or 16
    int bRow = tid >> 3;             // 0..31
    int bCol = (tid & 7) * 16;       // 0..112

    const float* Ag = A + ((size_t)by * 128 + aRow) * K + aCol;
    const float* Bg = B + (size_t)bRow * N + (size_t)bx * 128 + bCol;

    float acc[4][4][4];
#pragma unroll
    for (int mi = 0; mi < 4; mi++)
#pragma unroll
        for (int ni = 0; ni < 4; ni++)
#pragma unroll
            for (int r = 0; r < 4; r++) acc[mi][ni][r] = 0.f;

    int lr = lane >> 2;   // 0..7
    int lc = lane & 3;    // 0..3

    for (int k0 = 0; k0 < K; k0 += 32) {
        // load A 128x32
#pragma unroll
        for (int c = 0; c < 4; c++) {
            float4 a4 = *(const float4*)(Ag + k0 + c * 4);
            As[aRow][aCol + c * 4 + 0] = f2tf32(a4.x);
            As[aRow][aCol + c * 4 + 1] = f2tf32(a4.y);
            As[aRow][aCol + c * 4 + 2] = f2tf32(a4.z);
            As[aRow][aCol + c * 4 + 3] = f2tf32(a4.w);
        }
        // load B 32x128
#pragma unroll
        for (int c = 0; c < 4; c++) {
            float4 b4 = *(const float4*)(Bg + (size_t)k0 * N + c * 4);
            Bs[bRow][bCol + c * 4 + 0] = f2tf32(b4.x);
            Bs[bRow][bCol + c * 4 + 1] = f2tf32(b4.y);
            Bs[bRow][bCol + c * 4 + 2] = f2tf32(b4.z);
            Bs[bRow][bCol + c * 4 + 3] = f2tf32(b4.w);
        }
        __syncthreads();

#pragma unroll
        for (int kk = 0; kk < 4; kk++) {
            uint32_t af[4][4];
            uint32_t bf[4][2];
#pragma unroll
            for (int mi = 0; mi < 4; mi++) {
                int r0 = wm * 64 + mi * 16 + lr;
                int c0 = kk * 8 + lc;
                af[mi][0] = As[r0][c0];
                af[mi][1] = As[r0 + 8][c0];
                af[mi][2] = As[r0][c0 + 4];
                af[mi][3] = As[r0 + 8][c0 + 4];
            }
#pragma unroll
            for (int ni = 0; ni < 4; ni++) {
                int kr = kk * 8 + lc;
                int nc = wn * 32 + ni * 8 + lr;
                bf[ni][0] = Bs[kr][nc];
                bf[ni][1] = Bs[kr + 4][nc];
            }
#pragma unroll
            for (int mi = 0; mi < 4; mi++)
#pragma unroll
                for (int ni = 0; ni < 4; ni++) {
                    asm volatile(
                        "mma.sync.aligned.m16n8k8.row.col.f32.tf32.tf32.f32 "
                        "{%0,%1,%2,%3}, {%4,%5,%6,%7}, {%8,%9}, {%0,%1,%2,%3};"
                        : "+f"(acc[mi][ni][0]), "+f"(acc[mi][ni][1]),
                          "+f"(acc[mi][ni][2]), "+f"(acc[mi][ni][3])
                        : "r"(af[mi][0]), "r"(af[mi][1]), "r"(af[mi][2]), "r"(af[mi][3]),
                          "r"(bf[ni][0]), "r"(bf[ni][1]));
                }
        }
        __syncthreads();
    }

    // epilogue
#pragma unroll
    for (int mi = 0; mi < 4; mi++) {
#pragma unroll
        for (int ni = 0; ni < 4; ni++) {
            int row0 = by * 128 + wm * 64 + mi * 16 + lr;
            int col  = bx * 128 + wn * 32 + ni * 8 + lc * 2;
            float b0 = 0.f, b1 = 0.f;
            if (HASBIAS) { b0 = bias[col]; b1 = bias[col + 1]; }
            float v0 = acc[mi][ni][0] + b0;
            float v1 = acc[mi][ni][1] + b1;
            float v2 = acc[mi][ni][2] + b0;
            float v3 = acc[mi][ni][3] + b1;
            if (RELU) {
                v0 = fmaxf(v0, 0.f); v1 = fmaxf(v1, 0.f);
                v2 = fmaxf(v2, 0.f); v3 = fmaxf(v3, 0.f);
            }
            *(float2*)(C + (size_t)row0 * N + col)       = make_float2(v0, v1);
            *(float2*)(C + (size_t)(row0 + 8) * N + col) = make_float2(v2, v3);
        }
    }
}

// ---------------- batched score GEMM (scalar, unchanged) ----------------
__global__ void __launch_bounds__(256) score_kernel(
    const float* __restrict__ heads, const float* __restrict__ rk,
    const float* __restrict__ uv, float* __restrict__ out, int mode)
{
    int i0 = blockIdx.x * 64;
    int j0 = blockIdx.y * 64;
    int bh = blockIdx.z;
    int b = bh / NHEAD, n = bh % NHEAD;

    __shared__ float sQ[64][68];
    __shared__ float sK[64][68];

    int tid = threadIdx.x;
    {
        int i = tid >> 2;
        int dbase = (tid & 3) * 16;
        const float* qrow = heads + ((size_t)(MLEN + i0 + i) * BATCH + b) * 3072 + n * 64;
        const float* uvp = uv + n * 64;
        const float* krow;
        if (mode == 0) krow = heads + ((size_t)(j0 + i) * BATCH + b) * 3072 + 1024 + n * 64;
        else           krow = rk + (size_t)(j0 + i) * 1024 + n * 64;
#pragma unroll
        for (int c = 0; c < 4; c++) {
            float4 q4 = *(const float4*)(qrow + dbase + c * 4);
            float4 u4 = *(const float4*)(uvp + dbase + c * 4);
            float4 k4 = *(const float4*)(krow + dbase + c * 4);
            sQ[dbase + c * 4 + 0][i] = q4.x + u4.x;
            sQ[dbase + c * 4 + 1][i] = q4.y + u4.y;
            sQ[dbase + c * 4 + 2][i] = q4.z + u4.z;
            sQ[dbase + c * 4 + 3][i] = q4.w + u4.w;
            sK[dbase + c * 4 + 0][i] = k4.x;
            sK[dbase + c * 4 + 1][i] = k4.y;
            sK[dbase + c * 4 + 2][i] = k4.z;
            sK[dbase + c * 4 + 3][i] = k4.w;
        }
    }
    __syncthreads();

    int ty = tid >> 4, tx = tid & 15;
    float acc[4][4];
#pragma unroll
    for (int i = 0; i < 4; i++)
#pragma unroll
        for (int j = 0; j < 4; j++) acc[i][j] = 0.f;

#pragma unroll 8
    for (int d = 0; d < 64; d++) {
        float4 a = *(const float4*)&sQ[d][ty * 4];
        float4 bb = *(const float4*)&sK[d][tx * 4];
        float ar[4] = {a.x, a.y, a.z, a.w};
        float br[4] = {bb.x, bb.y, bb.z, bb.w};
#pragma unroll
        for (int i = 0; i < 4; i++)
#pragma unroll
            for (int j = 0; j < 4; j++) acc[i][j] += ar[i] * br[j];
    }

    float* obase = out + ((size_t)bh * QLEN + i0) * KLEN + j0;
#pragma unroll
    for (int i = 0; i < 4; i++) {
        float4 v = {acc[i][0], acc[i][1], acc[i][2], acc[i][3]};
        *(float4*)(obase + (size_t)(ty * 4 + i) * KLEN + tx * 4) = v;
    }
}

// ---------------- fused shift + mask + scale + softmax ----------------
__global__ void __launch_bounds__(256) softmax_kernel(float* ac, const float* __restrict__ bd) {
    int i = blockIdx.x;
    int bh = blockIdx.y;
    float* acrow = ac + ((size_t)bh * QLEN + i) * KLEN;
    const float* bdrow = bd + ((size_t)bh * QLEN + i) * KLEN;
    int tid = threadIdx.x;
    __shared__ float red[256];
    int jmax = i + MLEN;
    int shift = QLEN - 1 - i;
    float v[4];
    float m = -1e30f;
#pragma unroll
    for (int c = 0; c < 4; c++) {
        int j = c * 256 + tid;
        float s = (j <= jmax) ? 0.125f * (acrow[j] + bdrow[j + shift]) : -1e30f;
        v[c] = s;
        m = fmaxf(m, s);
    }
    red[tid] = m; __syncthreads();
    for (int o = 128; o > 0; o >>= 1) {
        if (tid < o) red[tid] = fmaxf(red[tid], red[tid + o]);
        __syncthreads();
    }
    m = red[0]; __syncthreads();
    float sum = 0.f;
#pragma unroll
    for (int c = 0; c < 4; c++) { v[c] = expf(v[c] - m); sum += v[c]; }
    red[tid] = sum; __syncthreads();
    for (int o = 128; o > 0; o >>= 1) {
        if (tid < o) red[tid] += red[tid + o];
        __syncthreads();
    }
    float inv = 1.0f / red[0];
#pragma unroll
    for (int c = 0; c < 4; c++) acrow[c * 256 + tid] = v[c] * inv;
}

// ---------------- AV ----------------
__global__ void __launch_bounds__(256) av_kernel(
    const float* __restrict__ attn, const float* __restrict__ heads, float* __restrict__ av)
{
    int i0 = blockIdx.x * 64;
    int bh = blockIdx.y;
    int b = bh / NHEAD, n = bh % NHEAD;

    __shared__ float sP[64][68];
    __shared__ float sV[64][64];

    int tid = threadIdx.x;
    int ty = tid >> 4, tx = tid & 15;
    float acc[4][4];
#pragma unroll
    for (int i = 0; i < 4; i++)
#pragma unroll
        for (int j = 0; j < 4; j++) acc[i][j] = 0.f;

    for (int j0 = 0; j0 < KLEN; j0 += 64) {
        {
            int i = tid >> 2;
            int jb = (tid & 3) * 16;
            const float* prow = attn + ((size_t)bh * QLEN + i0 + i) * KLEN + j0 + jb;
#pragma unroll
            for (int c = 0; c < 16; c++) sP[jb + c][i] = prow[c];

            int j = tid >> 2;
            int db = (tid & 3) * 16;
            const float* vrow = heads + ((size_t)(j0 + j) * BATCH + b) * 3072 + 2048 + n * 64 + db;
#pragma unroll
            for (int c = 0; c < 4; c++)
                *(float4*)&sV[j][db + c * 4] = *(const float4*)(vrow + c * 4);
        }
        __syncthreads();
#pragma unroll 8
        for (int j = 0; j < 64; j++) {
            float4 p = *(const float4*)&sP[j][ty * 4];
            float4 vv = *(const float4*)&sV[j][tx * 4];
            float pr[4] = {p.x, p.y, p.z, p.w};
            float vr[4] = {vv.x, vv.y, vv.z, vv.w};
#pragma unroll
            for (int i = 0; i < 4; i++)
#pragma unroll
                for (int d = 0; d < 4; d++) acc[i][d] += pr[i] * vr[d];
        }
        __syncthreads();
    }

#pragma unroll
    for (int i = 0; i < 4; i++) {
        float4 v = {acc[i][0], acc[i][1], acc[i][2], acc[i][3]};
        *(float4*)(av + ((size_t)(i0 + ty * 4 + i) * BATCH + b) * DMODEL + n * 64 + tx * 4) = v;
    }
}

// ---------------- residual add + LayerNorm ----------------
__global__ void __launch_bounds__(256) add_ln_kernel(
    float* __restrict__ h, const float* __restrict__ t,
    const float* __restrict__ g, const float* __restrict__ b)
{
    int row = blockIdx.x;
    int tid = threadIdx.x;
    __shared__ float rs[256], rs2[256];
    float x[4];
    float s = 0.f, ss = 0.f;
#pragma unroll
    for (int c = 0; c < 4; c++) {
        int d = c * 256 + tid;
        float v = h[(size_t)row * 1024 + d] + t[(size_t)row * 1024 + d];
        x[c] = v; s += v; ss += v * v;
    }
    rs[tid] = s; rs2[tid] = ss; __syncthreads();
    for (int o = 128; o > 0; o >>= 1) {
        if (tid < o) { rs[tid] += rs[tid + o]; rs2[tid] += rs2[tid + o]; }
        __syncthreads();
    }
    float mu = rs[0] * (1.0f / 1024.0f);
    float var = rs2[0] * (1.0f / 1024.0f) - mu * mu;
    float inv = rsqrtf(var + 1e-5f);
#pragma unroll
    for (int c = 0; c < 4; c++) {
        int d = c * 256 + tid;
        h[(size_t)row * 1024 + d] = (x[c] - mu) * inv * g[d] + b[d];
    }
}

// ---------------- launch ----------------
extern "C" void kernel_launch(void* const* d_in, const int* in_sizes, int n_in,
                              void* d_out, int out_size) {
    (void)in_sizes; (void)n_in; (void)out_size;
    const float* x     = (const float*)d_in[0];
    const float* mems  = (const float*)d_in[1];
    const float* u     = (const float*)d_in[2];
    const float* v     = (const float*)d_in[3];
    const float* W_qkv = (const float*)d_in[4];
    const float* W_o   = (const float*)d_in[5];
    const float* W_r   = (const float*)d_in[6];
    const float* ln1_g = (const float*)d_in[7];
    const float* ln1_b = (const float*)d_in[8];
    const float* W1    = (const float*)d_in[9];
    const float* b1    = (const float*)d_in[10];
    const float* W2    = (const float*)d_in[11];
    const float* b2    = (const float*)d_in[12];
    const float* ln2_g = (const float*)d_in[13];
    const float* ln2_b = (const float*)d_in[14];

    float *cat, *heads, *r, *rk, *ac, *bd, *av, *tmp, *h, *ff;
    cudaGetSymbolAddress((void**)&cat,   g_cat);
    cudaGetSymbolAddress((void**)&heads, g_heads);
    cudaGetSymbolAddress((void**)&r,     g_r);
    cudaGetSymbolAddress((void**)&rk,    g_rk);
    cudaGetSymbolAddress((void**)&ac,    g_ac);
    cudaGetSymbolAddress((void**)&bd,    g_bd);
    cudaGetSymbolAddress((void**)&av,    g_av);
    cudaGetSymbolAddress((void**)&tmp,   g_tmp);
    cudaGetSymbolAddress((void**)&h,     g_h);
    cudaGetSymbolAddress((void**)&ff,    g_ff);

    posemb_kernel<<<4096, 256>>>(r);
    copy4_kernel<<<2048, 256>>>((float4*)h, (const float4*)x);

    for (int l = 0; l < NLAYER; l++) {
        concat_kernel<<<4096, 256>>>((float4*)cat,
                                     (const float4*)(mems + (size_t)l * MLEN * BATCH * DMODEL),
                                     (const float4*)h);
        tf32gemm_kernel<0,0><<<dim3(3072/128, 4096/128), 256>>>(
            cat, W_qkv + (size_t)l * DMODEL * 3072, nullptr, heads, 4096, 3072, 1024);
        tf32gemm_kernel<0,0><<<dim3(8, 8), 256>>>(
            r, W_r + (size_t)l * DMODEL * DMODEL, nullptr, rk, 1024, 1024, 1024);
        score_kernel<<<dim3(QLEN/64, KLEN/64, BH), 256>>>(heads, rk, u, ac, 0);
        score_kernel<<<dim3(QLEN/64, KLEN/64, BH), 256>>>(heads, rk, v, bd, 1);
        softmax_kernel<<<dim3(QLEN, BH), 256>>>(ac, bd);
        av_kernel<<<dim3(QLEN/64, BH), 256>>>(ac, heads, av);
        tf32gemm_kernel<0,0><<<dim3(8, 16), 256>>>(
            av, W_o + (size_t)l * DMODEL * DMODEL, nullptr, tmp, 2048, 1024, 1024);
        add_ln_kernel<<<2048, 256>>>(h, tmp, ln1_g + (size_t)l * DMODEL, ln1_b + (size_t)l * DMODEL);
        tf32gemm_kernel<1,1><<<dim3(4096/128, 16), 256>>>(
            h, W1 + (size_t)l * DMODEL * DINNER, b1 + (size_t)l * DINNER, ff, 2048, 4096, 1024);
        tf32gemm_kernel<0,1><<<dim3(8, 16), 256>>>(
            ff, W2 + (size_t)l * DINNER * DMODEL, b2 + (size_t)l * DMODEL, tmp, 2048, 1024, 4096);
        add_ln_kernel<<<2048, 256>>>(h, tmp, ln2_g + (size_t)l * DMODEL, ln2_b + (size_t)l * DMODEL);
    }

    cudaMemcpyAsync(d_out, h, (size_t)QLEN * BATCH * DMODEL * sizeof(float),
                    cudaMemcpyDeviceToDevice);
}

// round 3
// speedup vs baseline: 1.9714x; 1.1133x over previous
#include <cuda_runtime.h>
#include <math.h>
#include <stdint.h>

#define QLEN 512
#define BATCH 4
#define DMODEL 1024
#define NLAYER 4
#define NHEAD 16
#define DHEAD 64
#define DINNER 4096
#define MLEN 512
#define KLEN 1024
#define BH (BATCH*NHEAD)

// ---------------- scratch ----------------
__device__ float g_cat[(size_t)KLEN*BATCH*DMODEL];
__device__ float g_heads[(size_t)KLEN*BATCH*3*DMODEL];
__device__ float g_r[(size_t)KLEN*DMODEL];
__device__ float g_rk[(size_t)KLEN*DMODEL];
__device__ float g_ac[(size_t)BH*QLEN*KLEN];
__device__ float g_bd[(size_t)BH*QLEN*KLEN];
__device__ float g_av[(size_t)QLEN*BATCH*DMODEL];
__device__ float g_tmp[(size_t)QLEN*BATCH*DMODEL];
__device__ float g_h[(size_t)QLEN*BATCH*DMODEL];
__device__ float g_ff[(size_t)QLEN*BATCH*DINNER];
__device__ float g_qu[(size_t)BH*QLEN*DHEAD];
__device__ float g_qv[(size_t)BH*QLEN*DHEAD];
__device__ float g_kc[(size_t)BH*KLEN*DHEAD];
__device__ float g_vc[(size_t)BH*KLEN*DHEAD];
__device__ float g_rkc[(size_t)NHEAD*KLEN*DHEAD];

__device__ __forceinline__ uint32_t f2tf32(float f) {
    uint32_t o;
    asm("cvt.rna.tf32.f32 %0, %1;" : "=r"(o) : "f"(f));
    return o;
}

#define MMA_TF32(d, a, b) \
    asm volatile("mma.sync.aligned.m16n8k8.row.col.f32.tf32.tf32.f32 " \
                 "{%0,%1,%2,%3}, {%4,%5,%6,%7}, {%8,%9}, {%0,%1,%2,%3};" \
                 : "+f"(d[0]), "+f"(d[1]), "+f"(d[2]), "+f"(d[3]) \
                 : "r"(a.x), "r"(a.y), "r"(a.z), "r"(a.w), "r"(b.x), "r"(b.y))

// ---------------- small kernels ----------------
__global__ void posemb_kernel(float* __restrict__ r) {
    int idx = blockIdx.x * 256 + threadIdx.x;
    int k = idx >> 10, d = idx & 1023;
    float pos = (float)(KLEN - 1 - k);
    int j = (d < 512) ? d : d - 512;
    float inv = expf(-((float)(2 * j) / 1024.0f) * 9.210340371976184f);
    float ang = pos * inv;
    r[idx] = (d < 512) ? sinf(ang) : cosf(ang);
}

__global__ void copy4_kernel(float4* __restrict__ dst, const float4* __restrict__ src) {
    size_t i = (size_t)blockIdx.x * 256 + threadIdx.x;
    dst[i] = src[i];
}

__global__ void concat_kernel(float4* __restrict__ cat, const float4* __restrict__ mem,
                              const float4* __restrict__ h) {
    size_t i = (size_t)blockIdx.x * 256 + threadIdx.x;
    const size_t half = (size_t)MLEN * BATCH * DMODEL / 4;
    cat[i] = (i < half) ? mem[i] : h[i - half];
}

// repack q+u, q+v into [bh][512][64]
__global__ void repack_quqv(const float* __restrict__ heads, const float* __restrict__ u,
                            const float* __restrict__ v, float* __restrict__ qu,
                            float* __restrict__ qv) {
    int idx = blockIdx.x * 256 + threadIdx.x;   // 64*512*16
    int d4 = idx & 15, i = (idx >> 4) & 511, bh = idx >> 13;
    int b = bh >> 4, n = bh & 15;
    float4 q = *(const float4*)(heads + ((size_t)((512 + i) * 4 + b)) * 3072 + n * 64 + d4 * 4);
    float4 uu = *(const float4*)(u + n * 64 + d4 * 4);
    float4 vv = *(const float4*)(v + n * 64 + d4 * 4);
    size_t o = ((size_t)bh * 512 + i) * 64 + d4 * 4;
    *(float4*)(qu + o) = make_float4(q.x + uu.x, q.y + uu.y, q.z + uu.z, q.w + uu.w);
    *(float4*)(qv + o) = make_float4(q.x + vv.x, q.y + vv.y, q.z + vv.z, q.w + vv.w);
}

// repack k, v into [bh][1024][64]
__global__ void repack_kv(const float* __restrict__ heads, float* __restrict__ kc,
                          float* __restrict__ vc) {
    int idx = blockIdx.x * 256 + threadIdx.x;   // 64*1024*16
    int d4 = idx & 15, j = (idx >> 4) & 1023, bh = idx >> 14;
    int b = bh >> 4, n = bh & 15;
    const float* base = heads + ((size_t)(j * 4 + b)) * 3072 + n * 64 + d4 * 4;
    float4 kx = *(const float4*)(base + 1024);
    float4 vx = *(const float4*)(base + 2048);
    size_t o = ((size_t)bh * 1024 + j) * 64 + d4 * 4;
    *(float4*)(kc + o) = kx;
    *(float4*)(vc + o) = vx;
}

// repack rk into [n][1024][64]
__global__ void repack_rk(const float* __restrict__ rk, float* __restrict__ rkc) {
    int idx = blockIdx.x * 256 + threadIdx.x;   // 16*1024*16
    int d4 = idx & 15, j = (idx >> 4) & 1023, n = idx >> 14;
    *(float4*)(rkc + ((size_t)n * 1024 + j) * 64 + d4 * 4) =
        *(const float4*)(rk + (size_t)j * 1024 + n * 64 + d4 * 4);
}

// ---------------- NT GEMM: C = A[M,K] @ B[K,N], permuted smem, tf32 MMA ----------------
// tile 128x128, BK=32, 8 warps (2M x 4N), warp 64x32
template<int RELU, int HASBIAS>
__global__ void __launch_bounds__(256, 2) gemm_nt(
    const float* __restrict__ A, const float* __restrict__ B,
    const float* __restrict__ bias, float* __restrict__ C,
    int K, int lda, int ldb, int ldc)
{
    __shared__ uint32_t Ap[4224];   // 32 blocks * 132
    __shared__ uint32_t Bp[4224];   // 64 blocks * 66
    const int tid = threadIdx.x, lane = tid & 31;
    const int warp = tid >> 5, wm = warp >> 2, wn = warp & 3;
    const int bx = blockIdx.x, by = blockIdx.y;

    const int ar = tid >> 1, akb = (tid & 1) * 16;
    const int a_wm = ar >> 6, a_mi = (ar >> 4) & 3, a_lr = ar & 7, a_rh = (ar >> 3) & 1;
    const float* Ag = A + (size_t)(by * 128 + ar) * lda + akb;

    const int bk = tid & 31, bn0 = (tid >> 5) * 16;
    const int b_kk = bk >> 3, b_lc = bk & 3, b_kh = (bk >> 2) & 1;
    const float* Bg = B + (size_t)bk * ldb + bx * 128 + bn0;

    float acc[4][4][4];
#pragma unroll
    for (int mi = 0; mi < 4; mi++)
#pragma unroll
        for (int ni = 0; ni < 4; ni++)
#pragma unroll
            for (int r = 0; r < 4; r++) acc[mi][ni][r] = 0.f;

    const int lr = lane >> 2, lc = lane & 3;

    for (int k0 = 0; k0 < K; k0 += 32) {
#pragma unroll
        for (int c = 0; c < 4; c++) {
            float4 a4 = *(const float4*)(Ag + k0 + c * 4);
            float va[4] = {a4.x, a4.y, a4.z, a4.w};
#pragma unroll
            for (int e = 0; e < 4; e++) {
                int k = akb + c * 4 + e;
                Ap[((a_wm * 4 + (k >> 3)) * 4 + a_mi) * 132 +
                   (a_lr * 4 + (k & 3)) * 4 + a_rh + 2 * ((k >> 2) & 1)] = f2tf32(va[e]);
            }
        }
#pragma unroll
        for (int c = 0; c < 4; c++) {
            float4 b4 = *(const float4*)(Bg + (size_t)k0 * ldb + c * 4);
            float vb[4] = {b4.x, b4.y, b4.z, b4.w};
#pragma unroll
            for (int e = 0; e < 4; e++) {
                int n = bn0 + c * 4 + e;
                Bp[(((n >> 5) * 4 + b_kk) * 4 + ((n >> 3) & 3)) * 66 +
                   ((n & 7) * 4 + b_lc) * 2 + b_kh] = f2tf32(vb[e]);
            }
        }
        __syncthreads();
#pragma unroll
        for (int kk = 0; kk < 4; kk++) {
            uint4 af[4]; uint2 bf[4];
#pragma unroll
            for (int mi = 0; mi < 4; mi++)
                af[mi] = *(const uint4*)&Ap[((wm * 4 + kk) * 4 + mi) * 132 + lane * 4];
#pragma unroll
            for (int ni = 0; ni < 4; ni++)
                bf[ni] = *(const uint2*)&Bp[((wn * 4 + kk) * 4 + ni) * 66 + lane * 2];
#pragma unroll
            for (int mi = 0; mi < 4; mi++)
#pragma unroll
                for (int ni = 0; ni < 4; ni++) MMA_TF32(acc[mi][ni], af[mi], bf[ni]);
        }
        __syncthreads();
    }

#pragma unroll
    for (int mi = 0; mi < 4; mi++) {
#pragma unroll
        for (int ni = 0; ni < 4; ni++) {
            int row0 = by * 128 + wm * 64 + mi * 16 + lr;
            int col  = bx * 128 + wn * 32 + ni * 8 + lc * 2;
            float b0 = 0.f, b1 = 0.f;
            if (HASBIAS) { b0 = bias[col]; b1 = bias[col + 1]; }
            float v0 = acc[mi][ni][0] + b0, v1 = acc[mi][ni][1] + b1;
            float v2 = acc[mi][ni][2] + b0, v3 = acc[mi][ni][3] + b1;
            if (RELU) {
                v0 = fmaxf(v0, 0.f); v1 = fmaxf(v1, 0.f);
                v2 = fmaxf(v2, 0.f); v3 = fmaxf(v3, 0.f);
            }
            *(float2*)(C + (size_t)row0 * ldc + col)       = make_float2(v0, v1);
            *(float2*)(C + (size_t)(row0 + 8) * ldc + col) = make_float2(v2, v3);
        }
    }
}

// ---------------- score MMA: out[bh,i,j] = A[bh,i,:] . B[*,j,:]  (A @ B^T, K=64) ----------
// mode 0: AC (B per bh, skip fully-masked tiles)   mode 1: BD raw (B per head)
__global__ void __launch_bounds__(256, 2) score_mma(
    const float* __restrict__ Qb, const float* __restrict__ Kb,
    float* __restrict__ out, int mode)
{
    const int bx = blockIdx.x, by = blockIdx.y, bh = blockIdx.z;
    const int i0 = by * 128, j0 = bx * 128;
    if (mode == 0) { if (j0 >= i0 + 640) return; }
    else           { if (i0 + j0 < 257) return; }
    const float* A = Qb + (size_t)bh * QLEN * 64;
    const float* B = Kb + (size_t)(mode ? (bh & 15) : bh) * KLEN * 64;

    __shared__ uint32_t Ap[4224];
    __shared__ uint32_t Bp[4224];
    const int tid = threadIdx.x, lane = tid & 31;
    const int warp = tid >> 5, wm = warp >> 2, wn = warp & 3;

    const int ar = tid >> 1, akb = (tid & 1) * 16;
    const int a_wm = ar >> 6, a_mi = (ar >> 4) & 3, a_lr = ar & 7, a_rh = (ar >> 3) & 1;
    const float* Ag = A + (size_t)(i0 + ar) * 64 + akb;
    const float* Bg = B + (size_t)(j0 + ar) * 64 + akb;   // B rows are n (j)
    const int b_wn = ar >> 5, b_ni = (ar >> 3) & 3, b_lnr = ar & 7;

    float acc[4][4][4];
#pragma unroll
    for (int mi = 0; mi < 4; mi++)
#pragma unroll
        for (int ni = 0; ni < 4; ni++)
#pragma unroll
            for (int r = 0; r < 4; r++) acc[mi][ni][r] = 0.f;

    const int lr = lane >> 2, lc = lane & 3;

#pragma unroll
    for (int k0 = 0; k0 < 64; k0 += 32) {
#pragma unroll
        for (int c = 0; c < 4; c++) {
            float4 a4 = *(const float4*)(Ag + k0 + c * 4);
            float4 b4 = *(const float4*)(Bg + k0 + c * 4);
            float va[4] = {a4.x, a4.y, a4.z, a4.w};
            float vb[4] = {b4.x, b4.y, b4.z, b4.w};
#pragma unroll
            for (int e = 0; e < 4; e++) {
                int k = akb + c * 4 + e;
                int kk = k >> 3, klc = k & 3, kh = (k >> 2) & 1;
                Ap[((a_wm * 4 + kk) * 4 + a_mi) * 132 +
                   (a_lr * 4 + klc) * 4 + a_rh + 2 * kh] = f2tf32(va[e]);
                Bp[((b_wn * 4 + kk) * 4 + b_ni) * 66 +
                   (b_lnr * 4 + klc) * 2 + kh] = f2tf32(vb[e]);
            }
        }
        __syncthreads();
#pragma unroll
        for (int kk = 0; kk < 4; kk++) {
            uint4 af[4]; uint2 bf[4];
#pragma unroll
            for (int mi = 0; mi < 4; mi++)
                af[mi] = *(const uint4*)&Ap[((wm * 4 + kk) * 4 + mi) * 132 + lane * 4];
#pragma unroll
            for (int ni = 0; ni < 4; ni++)
                bf[ni] = *(const uint2*)&Bp[((wn * 4 + kk) * 4 + ni) * 66 + lane * 2];
#pragma unroll
            for (int mi = 0; mi < 4; mi++)
#pragma unroll
                for (int ni = 0; ni < 4; ni++) MMA_TF32(acc[mi][ni], af[mi], bf[ni]);
        }
        __syncthreads();
    }

    float* ob = out + (size_t)bh * QLEN * KLEN;
#pragma unroll
    for (int mi = 0; mi < 4; mi++)
#pragma unroll
        for (int ni = 0; ni < 4; ni++) {
            int row0 = i0 + wm * 64 + mi * 16 + lr;
            int col  = j0 + wn * 32 + ni * 8 + lc * 2;
            *(float2*)(ob + (size_t)row0 * KLEN + col) =
                make_float2(acc[mi][ni][0], acc[mi][ni][1]);
            *(float2*)(ob + (size_t)(row0 + 8) * KLEN + col) =
                make_float2(acc[mi][ni][2], acc[mi][ni][3]);
        }
}

// ---------------- softmax (shift+mask+scale fused) ----------------
__global__ void __launch_bounds__(256) softmax_kernel(float* ac, const float* __restrict__ bd) {
    int i = blockIdx.x;
    int bh = blockIdx.y;
    float* acrow = ac + ((size_t)bh * QLEN + i) * KLEN;
    const float* bdrow = bd + ((size_t)bh * QLEN + i) * KLEN;
    int tid = threadIdx.x;
    __shared__ float red[256];
    int jmax = i + MLEN;
    int shift = QLEN - 1 - i;
    float v[4];
    float m = -1e30f;
#pragma unroll
    for (int c = 0; c < 4; c++) {
        int j = c * 256 + tid;
        float s = (j <= jmax) ? 0.125f * (acrow[j] + bdrow[j + shift]) : -1e30f;
        v[c] = s;
        m = fmaxf(m, s);
    }
    red[tid] = m; __syncthreads();
    for (int o = 128; o > 0; o >>= 1) {
        if (tid < o) red[tid] = fmaxf(red[tid], red[tid + o]);
        __syncthreads();
    }
    m = red[0]; __syncthreads();
    float sum = 0.f;
#pragma unroll
    for (int c = 0; c < 4; c++) { v[c] = expf(v[c] - m); sum += v[c]; }
    red[tid] = sum; __syncthreads();
    for (int o = 128; o > 0; o >>= 1) {
        if (tid < o) red[tid] += red[tid + o];
        __syncthreads();
    }
    float inv = 1.0f / red[0];
#pragma unroll
    for (int c = 0; c < 4; c++) acrow[c * 256 + tid] = v[c] * inv;
}

// ---------------- AV MMA: av[i,b,n*64+d] = P[bh,i,:kmax] @ V[bh,:,d] ----------------
// tile 128(M) x 64(N), 8 warps (4M x 2N), warp 32x32
__global__ void __launch_bounds__(256, 2) av_mma(
    const float* __restrict__ P, const float* __restrict__ V, float* __restrict__ av)
{
    const int by = blockIdx.x, bh = blockIdx.y;
    const int b = bh >> 4, n = bh & 15;
    const float* A = P + (size_t)bh * QLEN * KLEN + (size_t)by * 128 * KLEN;
    const float* Bv = V + (size_t)bh * KLEN * 64;
    const int kmax = min(KLEN, by * 128 + 640);

    __shared__ uint32_t Ap[4224];   // [wm4][kk4][mi2]*132
    __shared__ uint32_t Bp[2112];   // [wn2][kk4][ni4]*66
    const int tid = threadIdx.x, lane = tid & 31;
    const int warp = tid >> 5, wm = warp >> 1, wn = warp & 1;

    const int ar = tid >> 1, akb = (tid & 1) * 16;
    const int a_wm = ar >> 5, a_mi = (ar >> 4) & 1, a_lr = ar & 7, a_rh = (ar >> 3) & 1;
    const float* Ag = A + (size_t)ar * KLEN + akb;

    const int bk = tid & 31, bn0 = (tid >> 5) * 8;
    const int b_kk = bk >> 3, b_lc = bk & 3, b_kh = (bk >> 2) & 1;
    const float* Bg = Bv + (size_t)bk * 64 + bn0;

    float acc[2][4][4];
#pragma unroll
    for (int mi = 0; mi < 2; mi++)
#pragma unroll
        for (int ni = 0; ni < 4; ni++)
#pragma unroll
            for (int r = 0; r < 4; r++) acc[mi][ni][r] = 0.f;

    const int lr = lane >> 2, lc = lane & 3;

    for (int k0 = 0; k0 < kmax; k0 += 32) {
#pragma unroll
        for (int c = 0; c < 4; c++) {
            float4 a4 = *(const float4*)(Ag + k0 + c * 4);
            float va[4] = {a4.x, a4.y, a4.z, a4.w};
#pragma unroll
            for (int e = 0; e < 4; e++) {
                int k = akb + c * 4 + e;
                Ap[((a_wm * 4 + (k >> 3)) * 2 + a_mi) * 132 +
                   (a_lr * 4 + (k & 3)) * 4 + a_rh + 2 * ((k >> 2) & 1)] = f2tf32(va[e]);
            }
        }
#pragma unroll
        for (int c = 0; c < 2; c++) {
            float4 b4 = *(const float4*)(Bg + (size_t)k0 * 64 + c * 4);
            float vb[4] = {b4.x, b4.y, b4.z, b4.w};
#pragma unroll
            for (int e = 0; e < 4; e++) {
                int nn = bn0 + c * 4 + e;
                Bp[(((nn >> 5) * 4 + b_kk) * 4 + ((nn >> 3) & 3)) * 66 +
                   ((nn & 7) * 4 + b_lc) * 2 + b_kh] = f2tf32(vb[e]);
            }
        }
        __syncthreads();
#pragma unroll
        for (int kk = 0; kk < 4; kk++) {
            uint4 af[2]; uint2 bf[4];
#pragma unroll
            for (int mi = 0; mi < 2; mi++)
                af[mi] = *(const uint4*)&Ap[((wm * 4 + kk) * 2 + mi) * 132 + lane * 4];
#pragma unroll
            for (int ni = 0; ni < 4; ni++)
                bf[ni] = *(const uint2*)&Bp[((wn * 4 + kk) * 4 + ni) * 66 + lane * 2];
#pragma unroll
            for (int mi = 0; mi < 2; mi++)
#pragma unroll
                for (int ni = 0; ni < 4; ni++) MMA_TF32(acc[mi][ni], af[mi], bf[ni]);
        }
        __syncthreads();
    }

#pragma unroll
    for (int mi = 0; mi < 2; mi++)
#pragma unroll
        for (int ni = 0; ni < 4; ni++) {
            int row0 = by * 128 + wm * 32 + mi * 16 + lr;
            int col  = wn * 32 + ni * 8 + lc * 2;
            *(float2*)(av + ((size_t)row0 * 4 + b) * 1024 + n * 64 + col) =
                make_float2(acc[mi][ni][0], acc[mi][ni][1]);
            *(float2*)(av + ((size_t)(row0 + 8) * 4 + b) * 1024 + n * 64 + col) =
                make_float2(acc[mi][ni][2], acc[mi][ni][3]);
        }
}

// ---------------- residual add + LayerNorm ----------------
__global__ void __launch_bounds__(256) add_ln_kernel(
    float* __restrict__ h, const float* __restrict__ t,
    const float* __restrict__ g, const float* __restrict__ b)
{
    int row = blockIdx.x;
    int tid = threadIdx.x;
    __shared__ float rs[256], rs2[256];
    float x[4];
    float s = 0.f, ss = 0.f;
#pragma unroll
    for (int c = 0; c < 4; c++) {
        int d = c * 256 + tid;
        float v = h[(size_t)row * 1024 + d] + t[(size_t)row * 1024 + d];
        x[c] = v; s += v; ss += v * v;
    }
    rs[tid] = s; rs2[tid] = ss; __syncthreads();
    for (int o = 128; o > 0; o >>= 1) {
        if (tid < o) { rs[tid] += rs[tid + o]; rs2[tid] += rs2[tid + o]; }
        __syncthreads();
    }
    float mu = rs[0] * (1.0f / 1024.0f);
    float var = rs2[0] * (1.0f / 1024.0f) - mu * mu;
    float inv = rsqrtf(var + 1e-5f);
#pragma unroll
    for (int c = 0; c < 4; c++) {
        int d = c * 256 + tid;
        h[(size_t)row * 1024 + d] = (x[c] - mu) * inv * g[d] + b[d];
    }
}

// ---------------- launch ----------------
extern "C" void kernel_launch(void* const* d_in, const int* in_sizes, int n_in,
                              void* d_out, int out_size) {
    (void)in_sizes; (void)n_in; (void)out_size;
    const float* x     = (const float*)d_in[0];
    const float* mems  = (const float*)d_in[1];
    const float* u     = (const float*)d_in[2];
    const float* v     = (const float*)d_in[3];
    const float* W_qkv = (const float*)d_in[4];
    const float* W_o   = (const float*)d_in[5];
    const float* W_r   = (const float*)d_in[6];
    const float* ln1_g = (const float*)d_in[7];
    const float* ln1_b = (const float*)d_in[8];
    const float* W1    = (const float*)d_in[9];
    const float* b1    = (const float*)d_in[10];
    const float* W2    = (const float*)d_in[11];
    const float* b2    = (const float*)d_in[12];
    const float* ln2_g = (const float*)d_in[13];
    const float* ln2_b = (const float*)d_in[14];

    float *cat, *heads, *r, *rk, *ac, *bd, *av, *tmp, *h, *ff, *qu, *qv, *kc, *vc, *rkc;
    cudaGetSymbolAddress((void**)&cat,   g_cat);
    cudaGetSymbolAddress((void**)&heads, g_heads);
    cudaGetSymbolAddress((void**)&r,     g_r);
    cudaGetSymbolAddress((void**)&rk,    g_rk);
    cudaGetSymbolAddress((void**)&ac,    g_ac);
    cudaGetSymbolAddress((void**)&bd,    g_bd);
    cudaGetSymbolAddress((void**)&av,    g_av);
    cudaGetSymbolAddress((void**)&tmp,   g_tmp);
    cudaGetSymbolAddress((void**)&h,     g_h);
    cudaGetSymbolAddress((void**)&ff,    g_ff);
    cudaGetSymbolAddress((void**)&qu,    g_qu);
    cudaGetSymbolAddress((void**)&qv,    g_qv);
    cudaGetSymbolAddress((void**)&kc,    g_kc);
    cudaGetSymbolAddress((void**)&vc,    g_vc);
    cudaGetSymbolAddress((void**)&rkc,   g_rkc);

    posemb_kernel<<<4096, 256>>>(r);
    copy4_kernel<<<2048, 256>>>((float4*)h, (const float4*)x);

    for (int l = 0; l < NLAYER; l++) {
        const float* Wq = W_qkv + (size_t)l * DMODEL * 3072;
        concat_kernel<<<4096, 256>>>((float4*)cat,
                                     (const float4*)(mems + (size_t)l * MLEN * BATCH * DMODEL),
                                     (const float4*)h);
        // K,V for all 4096 rows (cols 1024..3071)
        gemm_nt<0,0><<<dim3(16, 32), 256>>>(cat, Wq + 1024, nullptr, heads + 1024,
                                            1024, 1024, 3072, 3072);
        // Q only for last 2048 rows (cols 0..1023)
        gemm_nt<0,0><<<dim3(8, 16), 256>>>(cat + (size_t)2048 * 1024, Wq, nullptr,
                                           heads + (size_t)2048 * 3072,
                                           1024, 1024, 3072, 3072);
        // rk
        gemm_nt<0,0><<<dim3(8, 8), 256>>>(r, W_r + (size_t)l * DMODEL * DMODEL, nullptr, rk,
                                          1024, 1024, 1024, 1024);
        // repacks
        repack_quqv<<<2048, 256>>>(heads, u, v, qu, qv);
        repack_kv<<<4096, 256>>>(heads, kc, vc);
        repack_rk<<<1024, 256>>>(rk, rkc);
        // scores
        score_mma<<<dim3(8, 4, BH), 256>>>(qu, kc, ac, 0);
        score_mma<<<dim3(8, 4, BH), 256>>>(qv, rkc, bd, 1);
        // softmax
        softmax_kernel<<<dim3(QLEN, BH), 256>>>(ac, bd);
        // AV
        av_mma<<<dim3(4, BH), 256>>>(ac, vc, av);
        // O projection
        gemm_nt<0,0><<<dim3(8, 16), 256>>>(av, W_o + (size_t)l * DMODEL * DMODEL, nullptr, tmp,
                                           1024, 1024, 1024, 1024);
        add_ln_kernel<<<2048, 256>>>(h, tmp, ln1_g + (size_t)l * DMODEL, ln1_b + (size_t)l * DMODEL);
        // FFN
        gemm_nt<1,1><<<dim3(32, 16), 256>>>(h, W1 + (size_t)l * DMODEL * DINNER,
                                            b1 + (size_t)l * DINNER, ff,
                                            1024, 1024, 4096, 4096);
        gemm_nt<0,1><<<dim3(8, 16), 256>>>(ff, W2 + (size_t)l * DINNER * DMODEL,
                                           b2 + (size_t)l * DMODEL, tmp,
                                           4096, 4096, 1024, 1024);
        add_ln_kernel<<<2048, 256>>>(h, tmp, ln2_g + (size_t)l * DMODEL, ln2_b + (size_t)l * DMODEL);
    }

    cudaMemcpyAsync(d_out, h, (size_t)QLEN * BATCH * DMODEL * sizeof(float),
                    cudaMemcpyDeviceToDevice);
}